// round 1
// baseline (speedup 1.0000x reference)
#include <cuda_runtime.h>
#include <math.h>

#define BATCH 16
#define CCH   256
#define NSP   4096
#define M3    768
#define NGRP  4
#define CPG   64
#define NH    8
#define HD    32

// ---------------- scratch (device globals; no allocations allowed) ----------
__device__ float g_qkv[BATCH * M3 * NSP];      // 201 MB: q,k,v per batch
__device__ float g_attout[BATCH * CCH * NSP];  // 67 MB: attention output
__device__ float g_att[BATCH * NH * HD * HD];  // 32x32 per (b,h)
__device__ float g_mu[BATCH * NGRP];
__device__ float g_rsig[BATCH * NGRP];

// ---------------- 1) GroupNorm statistics ----------------------------------
// grid = 64 (b*4+g), block = 1024. Group = 64 contiguous channels * 4096.
__global__ __launch_bounds__(1024) void gn_stats_kernel(const float* __restrict__ x)
{
    int bg = blockIdx.x;
    const float4* p = (const float4*)(x + (size_t)bg * CPG * NSP);
    // 64*4096/4 = 65536 float4
    float s = 0.f, sq = 0.f;
    for (int i = threadIdx.x; i < 65536; i += 1024) {
        float4 v = p[i];
        s  += v.x + v.y + v.z + v.w;
        sq += v.x * v.x + v.y * v.y + v.z * v.z + v.w * v.w;
    }
    __shared__ float ss[32], ssq[32];
    #pragma unroll
    for (int o = 16; o; o >>= 1) {
        s  += __shfl_down_sync(0xffffffffu, s, o);
        sq += __shfl_down_sync(0xffffffffu, sq, o);
    }
    int w = threadIdx.x >> 5, l = threadIdx.x & 31;
    if (l == 0) { ss[w] = s; ssq[w] = sq; }
    __syncthreads();
    if (w == 0) {
        s  = ss[l];
        sq = ssq[l];
        #pragma unroll
        for (int o = 16; o; o >>= 1) {
            s  += __shfl_down_sync(0xffffffffu, s, o);
            sq += __shfl_down_sync(0xffffffffu, sq, o);
        }
        if (l == 0) {
            const float inv = 1.0f / (float)(CPG * NSP);
            float mu  = s * inv;
            float var = sq * inv - mu * mu;
            g_mu[bg]   = mu;
            g_rsig[bg] = rsqrtf(var + 1e-5f);
        }
    }
}

// ---------------- 2/6) SGEMM 128x128x8, 256 threads, 8x8 per thread --------
// C[b][o][n] = sum_c A[o][c] * B[b][c][n]   (+ optional GN on B, bias on C)
template<int M, bool FUSE_GN, bool ADD_BIAS, bool B_SYM, bool C_SYM>
__global__ __launch_bounds__(256) void sgemm_kernel(
    const float* __restrict__ A,     // [M][256]
    const float* __restrict__ Bext,  // [BATCH][256][4096] (if !B_SYM)
    float*       __restrict__ Cext,  // [BATCH][M][4096]   (if !C_SYM)
    const float* __restrict__ gnw,
    const float* __restrict__ gnb,
    const float* __restrict__ bias)
{
    const int K = 256, N = NSP;
    int b = blockIdx.z;
    const float* Bbase = B_SYM ? g_attout : Bext;
    float*       Cbase = C_SYM ? g_qkv    : Cext;
    const float* Bp = Bbase + (size_t)b * K * N;
    float*       Cp = Cbase + (size_t)b * M * N;
    int m0 = blockIdx.y * 128, n0 = blockIdx.x * 128;

    __shared__ float As[8][128];
    __shared__ float Bs[8][128];

    int tid  = threadIdx.x;
    int arow = tid >> 1,  acol = (tid & 1) << 2;   // A: 128 rows x 8 cols
    int brow = tid >> 5,  bcol = (tid & 31) << 2;  // B: 8 rows x 128 cols
    int tm   = (tid >> 4) << 3;
    int tn   = (tid & 15) << 3;

    float acc[8][8];
    #pragma unroll
    for (int i = 0; i < 8; i++)
        #pragma unroll
        for (int j = 0; j < 8; j++) acc[i][j] = 0.f;

    for (int k0 = 0; k0 < K; k0 += 8) {
        float4 av = *(const float4*)(A + (size_t)(m0 + arow) * K + k0 + acol);
        As[acol + 0][arow] = av.x;
        As[acol + 1][arow] = av.y;
        As[acol + 2][arow] = av.z;
        As[acol + 3][arow] = av.w;

        int c = k0 + brow;
        float4 bv = *(const float4*)(Bp + (size_t)c * N + n0 + bcol);
        if (FUSE_GN) {
            int g = c >> 6;
            float rs = g_rsig[b * NGRP + g];
            float mu = g_mu[b * NGRP + g];
            float w  = gnw[c] * rs;
            float bb = gnb[c] - mu * w;
            bv.x = bv.x * w + bb;
            bv.y = bv.y * w + bb;
            bv.z = bv.z * w + bb;
            bv.w = bv.w * w + bb;
        }
        *(float4*)&Bs[brow][bcol] = bv;
        __syncthreads();

        #pragma unroll
        for (int kk = 0; kk < 8; kk++) {
            float4 a0 = *(const float4*)&As[kk][tm];
            float4 a1 = *(const float4*)&As[kk][tm + 4];
            float4 b0 = *(const float4*)&Bs[kk][tn];
            float4 b1 = *(const float4*)&Bs[kk][tn + 4];
            float ra[8] = {a0.x, a0.y, a0.z, a0.w, a1.x, a1.y, a1.z, a1.w};
            float rb[8] = {b0.x, b0.y, b0.z, b0.w, b1.x, b1.y, b1.z, b1.w};
            #pragma unroll
            for (int i = 0; i < 8; i++)
                #pragma unroll
                for (int j = 0; j < 8; j++)
                    acc[i][j] += ra[i] * rb[j];
        }
        __syncthreads();
    }

    #pragma unroll
    for (int i = 0; i < 8; i++) {
        float bvv = ADD_BIAS ? bias[m0 + tm + i] : 0.f;
        #pragma unroll
        for (int j = 0; j < 8; j += 4) {
            float4 o;
            o.x = acc[i][j + 0] + bvv;
            o.y = acc[i][j + 1] + bvv;
            o.z = acc[i][j + 2] + bvv;
            o.w = acc[i][j + 3] + bvv;
            *(float4*)(Cp + (size_t)(m0 + tm + i) * N + n0 + tn + j) = o;
        }
    }
}

// ---------------- 3) softmax over K rows (in place in g_qkv) ---------------
// grid = 4096 rows (b*256 + ch), block = 256, 16 floats/thread in registers.
__global__ __launch_bounds__(256) void softmax_kernel()
{
    int row = blockIdx.x;
    int b = row >> 8, ch = row & 255;
    float* p = g_qkv + (size_t)(b * M3 + CCH + ch) * NSP;
    float4* p4 = (float4*)p;

    float4 v[4];
    float mx = -3.4e38f;
    #pragma unroll
    for (int i = 0; i < 4; i++) {
        v[i] = p4[threadIdx.x + i * 256];
        mx = fmaxf(mx, fmaxf(fmaxf(v[i].x, v[i].y), fmaxf(v[i].z, v[i].w)));
    }
    __shared__ float sm[8], ssum[8];
    #pragma unroll
    for (int o = 16; o; o >>= 1) mx = fmaxf(mx, __shfl_xor_sync(0xffffffffu, mx, o));
    int w = threadIdx.x >> 5, l = threadIdx.x & 31;
    if (l == 0) sm[w] = mx;
    __syncthreads();
    mx = sm[0];
    #pragma unroll
    for (int i = 1; i < 8; i++) mx = fmaxf(mx, sm[i]);

    float s = 0.f;
    #pragma unroll
    for (int i = 0; i < 4; i++) {
        v[i].x = expf(v[i].x - mx);
        v[i].y = expf(v[i].y - mx);
        v[i].z = expf(v[i].z - mx);
        v[i].w = expf(v[i].w - mx);
        s += v[i].x + v[i].y + v[i].z + v[i].w;
    }
    #pragma unroll
    for (int o = 16; o; o >>= 1) s += __shfl_xor_sync(0xffffffffu, s, o);
    if (l == 0) ssum[w] = s;
    __syncthreads();
    s = 0.f;
    #pragma unroll
    for (int i = 0; i < 8; i++) s += ssum[i];
    float r = 1.0f / s;
    #pragma unroll
    for (int i = 0; i < 4; i++) {
        v[i].x *= r; v[i].y *= r; v[i].z *= r; v[i].w *= r;
        p4[threadIdx.x + i * 256] = v[i];
    }
}

// ---------------- 4) att[b,h,d,e] = sum_n k[d,n] * v[e,n] ------------------
// grid = 128 (b*8+h), block = 256 (2x2 outputs per thread), n tiles of 128.
__global__ __launch_bounds__(256) void att_kernel()
{
    int bh = blockIdx.x;
    int b = bh >> 3, h = bh & 7;
    const float* kp = g_qkv + (size_t)(b * M3 + CCH     + h * HD) * NSP;
    const float* vp = g_qkv + (size_t)(b * M3 + 2 * CCH + h * HD) * NSP;

    __shared__ float ks[128][33];
    __shared__ float vs[128][33];

    int tid = threadIdx.x;
    int d0 = (tid >> 4) << 1;   // 0..30 step 2
    int e0 = (tid & 15) << 1;   // 0..30 step 2
    float a00 = 0.f, a01 = 0.f, a10 = 0.f, a11 = 0.f;

    for (int n0 = 0; n0 < NSP; n0 += 128) {
        #pragma unroll
        for (int t = 0; t < 4; t++) {
            int lin = tid + t * 256;         // 0..1023
            int d   = lin >> 5;              // 0..31
            int nq  = (lin & 31) << 2;       // 0..124
            float4 kv = *(const float4*)(kp + (size_t)d * NSP + n0 + nq);
            ks[nq + 0][d] = kv.x; ks[nq + 1][d] = kv.y;
            ks[nq + 2][d] = kv.z; ks[nq + 3][d] = kv.w;
            float4 vv = *(const float4*)(vp + (size_t)d * NSP + n0 + nq);
            vs[nq + 0][d] = vv.x; vs[nq + 1][d] = vv.y;
            vs[nq + 2][d] = vv.z; vs[nq + 3][d] = vv.w;
        }
        __syncthreads();
        #pragma unroll 8
        for (int nn = 0; nn < 128; nn++) {
            float k0v = ks[nn][d0], k1v = ks[nn][d0 + 1];
            float v0v = vs[nn][e0], v1v = vs[nn][e0 + 1];
            a00 += k0v * v0v; a01 += k0v * v1v;
            a10 += k1v * v0v; a11 += k1v * v1v;
        }
        __syncthreads();
    }
    float* ap = g_att + (size_t)bh * HD * HD;
    ap[(d0 + 0) * HD + e0 + 0] = a00;
    ap[(d0 + 0) * HD + e0 + 1] = a01;
    ap[(d0 + 1) * HD + e0 + 0] = a10;
    ap[(d0 + 1) * HD + e0 + 1] = a11;
}

// ---------------- 5) out[b, h*32+e, n] = sum_d att[d,e] * q[d,n] -----------
// grid = (4096/32, 128 bh), block = 256: 32 n-lanes x 8 e-groups(4 e each).
__global__ __launch_bounds__(256) void outmul_kernel()
{
    int bh = blockIdx.y;
    int b = bh >> 3, h = bh & 7;
    int n  = blockIdx.x * 32 + (threadIdx.x & 31);
    int eg = threadIdx.x >> 5;   // 0..7

    __shared__ float4 att_s[32][8];  // [d][e/4]
    ((float4*)att_s)[threadIdx.x] = ((const float4*)(g_att + (size_t)bh * 1024))[threadIdx.x];
    __syncthreads();

    const float* qp = g_qkv + (size_t)(b * M3 + h * HD) * NSP + n;
    float acc0 = 0.f, acc1 = 0.f, acc2 = 0.f, acc3 = 0.f;
    #pragma unroll
    for (int d = 0; d < 32; d++) {
        float qv = qp[(size_t)d * NSP];
        float4 a = att_s[d][eg];
        acc0 += a.x * qv; acc1 += a.y * qv;
        acc2 += a.z * qv; acc3 += a.w * qv;
    }
    float* op = g_attout + (size_t)(b * CCH + h * HD + eg * 4) * NSP + n;
    op[0 * NSP] = acc0; op[1 * NSP] = acc1;
    op[2 * NSP] = acc2; op[3 * NSP] = acc3;
}

// ---------------- launch ----------------------------------------------------
extern "C" void kernel_launch(void* const* d_in, const int* in_sizes, int n_in,
                              void* d_out, int out_size)
{
    const float* x     = (const float*)d_in[0];
    const float* gnw   = (const float*)d_in[1];
    const float* gnb   = (const float*)d_in[2];
    const float* qkvw  = (const float*)d_in[3];
    const float* projw = (const float*)d_in[4];
    const float* projb = (const float*)d_in[5];
    float* out = (float*)d_out;

    gn_stats_kernel<<<BATCH * NGRP, 1024>>>(x);

    // QKV: M=768, GN fused into B-load, C -> g_qkv
    sgemm_kernel<M3, true, false, false, true>
        <<<dim3(NSP / 128, M3 / 128, BATCH), 256>>>(qkvw, x, nullptr, gnw, gnb, nullptr);

    softmax_kernel<<<BATCH * CCH, 256>>>();

    att_kernel<<<BATCH * NH, 256>>>();

    outmul_kernel<<<dim3(NSP / 32, BATCH * NH), 256>>>();

    // PROJ: M=256, B <- g_attout, bias, C -> d_out
    sgemm_kernel<CCH, false, true, true, false>
        <<<dim3(NSP / 128, CCH / 128, BATCH), 256>>>(projw, nullptr, out, nullptr, nullptr, projb);
}